// round 4
// baseline (speedup 1.0000x reference)
#include <cuda_runtime.h>
#include <cstdint>
#include <cstddef>

// NeRD pixel decoder, fully fused per image row, cp.async double-buffered.
//   Layer 0: implicit 5x5 conv as GEMM  [128 x 3202] @ [3202 x 256]  (tf32 mma)
//   Layers 1,2: [128 x 256] @ [256 x 256]                            (tf32 mma)
//   Head: [128 x 256] @ [256 x 3]                                    (scalar FMA)
// One CTA = one (batch, image-row): M = 128 pixels, N = 256 hidden.
//
// Prep kernels pre-convert xi (padded) and W0/W1/W2 to tf32-in-fp32 bits so the
// main kernel can stage operands with raw cp.async (no cvt on the hot path).
//
// Bank-conflict rules (derived R2):
//   k-major operand (A/B slabs): frag addr = lc*stride + lr -> stride%32==8
//   m-major operand (smH):       frag addr = lr*stride + lc -> stride%32==4

#define FC   128
#define PS   5
#define HID  256
#define OUTC 3
#define IMH  128
#define IMW  128
#define OMEGA 30.0f

#define THREADS 512

#define XPH 132                 // 128 + 2 pad each side (h)
#define XPW 136                 // 128 + 2 pad each side (w) + 4 -> stride%32==8
#define CHS (XPH * XPW)         // padded channel stride = 17952

#define SMH_STRIDE 260          // m-major, %32==4 -> conflict-free
#define SMA_STRIDE 136          // k-major, %32==8 -> conflict-free (matches XPW)
#define SMB_STRIDE 264          // k-major, %32==8 -> conflict-free

#define SMH_FLOATS (128 * SMH_STRIDE)   // 33280
#define SMA_FLOATS (32  * SMA_STRIDE)   // 4352
#define SMB_FLOATS (32  * SMB_STRIDE)   // 8448
// smA double-buffer aliases into smH (smH unused during layer 0)
#define SMEM_FLOATS (SMH_FLOATS + 2 * SMB_FLOATS)
#define SMEM_BYTES  (SMEM_FLOATS * 4)   // 200704 B < 227 KB

// ---- persistent scratch (static device arrays: allowed, no dynamic alloc) ----
__device__ float g_xi[2 * FC * XPH * XPW];   // 18.4 MB, tf32-rounded, zero-padded
__device__ float g_W0[3200 * HID];           // 3.28 MB, tf32-rounded
__device__ float g_W1[HID * HID];
__device__ float g_W2[HID * HID];

__device__ __forceinline__ unsigned f2tf(float f) {
    unsigned u;
    asm("cvt.rna.tf32.f32 %0, %1;" : "=r"(u) : "f"(f));
    return u;
}

__device__ __forceinline__ void cpa16(float* dst_smem, const float* src_gmem) {
    unsigned s = (unsigned)__cvta_generic_to_shared(dst_smem);
    asm volatile("cp.async.ca.shared.global [%0], [%1], 16;" :: "r"(s), "l"(src_gmem));
}
#define CP_COMMIT asm volatile("cp.async.commit_group;")
#define CP_WAIT0  asm volatile("cp.async.wait_group 0;")

// m16n8k8 tf32 mma, fp32 accumulate. Fragment layouts per PTX ISA:
//   A (16x8):  a0:(g,t) a1:(g+8,t) a2:(g,t+4) a3:(g+8,t+4)   g=lane>>2, t=lane&3
//   B (8x8):   b0:(k=t, n=g)  b1:(k=t+4, n=g)
//   C (16x8):  c0:(g,2t) c1:(g,2t+1) c2:(g+8,2t) c3:(g+8,2t+1)
__device__ __forceinline__ void mma8(float* c, const unsigned* a, unsigned b0, unsigned b1) {
    asm("mma.sync.aligned.m16n8k8.row.col.f32.tf32.tf32.f32 "
        "{%0,%1,%2,%3}, {%4,%5,%6,%7}, {%8,%9}, {%0,%1,%2,%3};"
        : "+f"(c[0]), "+f"(c[1]), "+f"(c[2]), "+f"(c[3])
        : "r"(a[0]), "r"(a[1]), "r"(a[2]), "r"(a[3]), "r"(b0), "r"(b1));
}

// ================= prep kernels =================
extern "C" __global__ void prep_xi_kernel(const float* __restrict__ xi) {
    int idx = blockIdx.x * blockDim.x + threadIdx.x;
    if (idx >= 2 * FC * XPH * XPW) return;
    const int wp = idx % XPW;
    const int t  = idx / XPW;
    const int hp = t % XPH;
    const int bc = t / XPH;                // b*FC + c
    const int h = hp - 2, w = wp - 2;
    float v = 0.f;
    if ((unsigned)h < IMH && (unsigned)w < IMW)
        v = xi[((size_t)bc * IMH + h) * IMW + w];
    g_xi[idx] = __uint_as_float(f2tf(v));
}

extern "C" __global__ void prep_w_kernel(const float* __restrict__ W0,
                                         const float* __restrict__ W1,
                                         const float* __restrict__ W2) {
    int idx = blockIdx.x * blockDim.x + threadIdx.x;
    if (idx < 3200 * HID) {
        g_W0[idx] = __uint_as_float(f2tf(W0[idx]));
    } else {
        int j = idx - 3200 * HID;
        if (j < HID * HID)          g_W1[j] = __uint_as_float(f2tf(W1[j]));
        else if (j < 2 * HID * HID) g_W2[j - HID * HID] = __uint_as_float(f2tf(W2[j - HID * HID]));
    }
}

// ================= main fused kernel =================
extern "C" __global__ void __launch_bounds__(THREADS, 1)
nerd_fused_kernel(const float* __restrict__ W0f,  // original fp32 W0 (coord rows)
                  const float* __restrict__ b0,
                  const float* __restrict__ b1,
                  const float* __restrict__ b2,
                  const float* __restrict__ W3, const float* __restrict__ b3,
                  float* __restrict__ out)
{
    extern __shared__ float smem[];
    float* smH = smem;                                        // [128][260]
    float* const smBb[2] = { smem + SMH_FLOATS, smem + SMH_FLOATS + SMB_FLOATS };
    float* const smAb[2] = { smem, smem + SMA_FLOATS };       // aliased into smH

    const int tid  = threadIdx.x;
    const int lane = tid & 31;
    const int warp = tid >> 5;             // 16 warps
    const int wm   = warp >> 2;            // m block of 32
    const int wn   = warp & 3;             // n block of 64
    const int lr   = lane >> 2;
    const int lc   = lane & 3;

    const int bx   = blockIdx.x;
    const int bimg = bx >> 7;
    const int hrow = bx & 127;

    const float* gxib = g_xi + (size_t)bimg * FC * CHS;

    float acc[64];
#pragma unroll
    for (int i = 0; i < 64; ++i) acc[i] = 0.f;

    // staging helpers
    auto stage_A = [&](int g, float* dst) {        // g = ph*4 + cb
        const int ph = g >> 2, cb = g & 3;
        const float* base = gxib + (size_t)(cb * 32) * CHS + (size_t)(hrow + ph) * XPW;
        for (int idx = tid; idx < 32 * 34; idx += THREADS) {   // 1088 float4
            const int c = idx / 34, f4 = idx - c * 34;
            cpa16(dst + c * SMA_STRIDE + f4 * 4, base + (size_t)c * CHS + f4 * 4);
        }
    };
    auto stage_B0 = [&](int it, float* dst) {      // it = (ph*4+cb)*5 + pw
        const int g = it / 5, pw = it - g * 5;
        const int ph = g >> 2, cb = g & 3;
        const float* wrow = g_W0 + (size_t)(cb * 32 * 25 + ph * 5 + pw) * HID;
        for (int idx = tid; idx < 2048; idx += THREADS) {      // 32 rows x 64 float4
            const int ci = idx >> 6, f4 = idx & 63;
            cpa16(dst + ci * SMB_STRIDE + f4 * 4, wrow + (size_t)ci * 25 * HID + f4 * 4);
        }
    };
    auto stage_BL = [&](const float* Wg, int kb, float* dst) {
        const float* wb = Wg + (size_t)kb * 32 * HID;
        for (int idx = tid; idx < 2048; idx += THREADS) {
            const int ci = idx >> 6, f4 = idx & 63;
            cpa16(dst + ci * SMB_STRIDE + f4 * 4, wb + (size_t)ci * HID + f4 * 4);
        }
    };

    // ================= Layer 0: 100 pipelined iterations =================
    stage_A(0, smAb[0]);
    stage_B0(0, smBb[0]);
    CP_COMMIT; CP_WAIT0; __syncthreads();

    for (int it = 0; it < 100; ++it) {
        const int g = it / 5, pw = it - g * 5;
        if (pw == 0 && g + 1 < 20) stage_A(g + 1, smAb[(g + 1) & 1]);
        if (it + 1 < 100)          stage_B0(it + 1, smBb[(it + 1) & 1]);
        CP_COMMIT;

        const float* sA = smAb[g & 1];
        const float* sB = smBb[it & 1];
#pragma unroll
        for (int kk = 0; kk < 4; ++kk) {
            const int k0 = kk * 8;
            unsigned a[2][4];
#pragma unroll
            for (int mt = 0; mt < 2; ++mt) {
                const int mbase = wm * 32 + mt * 16 + lr + pw;   // halo +2, pw-2
                a[mt][0] = __float_as_uint(sA[(k0 + lc)     * SMA_STRIDE + mbase]);
                a[mt][1] = __float_as_uint(sA[(k0 + lc)     * SMA_STRIDE + mbase + 8]);
                a[mt][2] = __float_as_uint(sA[(k0 + lc + 4) * SMA_STRIDE + mbase]);
                a[mt][3] = __float_as_uint(sA[(k0 + lc + 4) * SMA_STRIDE + mbase + 8]);
            }
#pragma unroll
            for (int nt = 0; nt < 8; ++nt) {
                const int n0 = wn * 64 + nt * 8 + lr;
                const unsigned bb0 = __float_as_uint(sB[(k0 + lc)     * SMB_STRIDE + n0]);
                const unsigned bb1 = __float_as_uint(sB[(k0 + lc + 4) * SMB_STRIDE + n0]);
                mma8(&acc[nt * 4],      a[0], bb0, bb1);
                mma8(&acc[32 + nt * 4], a[1], bb0, bb1);
            }
        }
        CP_WAIT0; __syncthreads();
    }

    // ---- layer-0 epilogue: + coords*W0[3200:3202] + b0, sin, -> smH ----
    {
        const float gy = -1.f + 2.f * (float)hrow * (1.f / 127.f);
#pragma unroll
        for (int mt = 0; mt < 2; ++mt)
#pragma unroll
            for (int nt = 0; nt < 8; ++nt)
#pragma unroll
                for (int i = 0; i < 4; ++i) {
                    const int m = wm * 32 + mt * 16 + lr + ((i >= 2) ? 8 : 0);
                    const int n = wn * 64 + nt * 8 + lc * 2 + (i & 1);
                    const float gx = -1.f + 2.f * (float)m * (1.f / 127.f);
                    float z = acc[mt * 32 + nt * 4 + i]
                            + gx * W0f[3200 * HID + n]
                            + gy * W0f[3201 * HID + n]
                            + b0[n];
                    smH[m * SMH_STRIDE + n] = __uint_as_float(f2tf(__sinf(OMEGA * z)));
                }
    }
    __syncthreads();

    // ================= Layers 1 and 2 (pipelined k-slabs) =================
    for (int L = 0; L < 2; ++L) {
        const float* Wg = L ? g_W2 : g_W1;
        const float* bl = L ? b2 : b1;
#pragma unroll
        for (int i = 0; i < 64; ++i) acc[i] = 0.f;

        stage_BL(Wg, 0, smBb[0]);
        CP_COMMIT; CP_WAIT0; __syncthreads();

        for (int kb = 0; kb < 8; ++kb) {
            if (kb + 1 < 8) stage_BL(Wg, kb + 1, smBb[(kb + 1) & 1]);
            CP_COMMIT;
            const float* sB = smBb[kb & 1];
#pragma unroll
            for (int kk = 0; kk < 4; ++kk) {
                const int k0 = kk * 8;
                const int kg = kb * 32 + k0;
                unsigned a[2][4];
#pragma unroll
                for (int mt = 0; mt < 2; ++mt) {
                    const int mbase = wm * 32 + mt * 16 + lr;
                    a[mt][0] = __float_as_uint(smH[(mbase)     * SMH_STRIDE + kg + lc]);
                    a[mt][1] = __float_as_uint(smH[(mbase + 8) * SMH_STRIDE + kg + lc]);
                    a[mt][2] = __float_as_uint(smH[(mbase)     * SMH_STRIDE + kg + lc + 4]);
                    a[mt][3] = __float_as_uint(smH[(mbase + 8) * SMH_STRIDE + kg + lc + 4]);
                }
#pragma unroll
                for (int nt = 0; nt < 8; ++nt) {
                    const int n0 = wn * 64 + nt * 8 + lr;
                    const unsigned bb0 = __float_as_uint(sB[(k0 + lc)     * SMB_STRIDE + n0]);
                    const unsigned bb1 = __float_as_uint(sB[(k0 + lc + 4) * SMB_STRIDE + n0]);
                    mma8(&acc[nt * 4],      a[0], bb0, bb1);
                    mma8(&acc[32 + nt * 4], a[1], bb0, bb1);
                }
            }
            CP_WAIT0; __syncthreads();
        }

#pragma unroll
        for (int mt = 0; mt < 2; ++mt)
#pragma unroll
            for (int nt = 0; nt < 8; ++nt)
#pragma unroll
                for (int i = 0; i < 4; ++i) {
                    const int m = wm * 32 + mt * 16 + lr + ((i >= 2) ? 8 : 0);
                    const int n = wn * 64 + nt * 8 + lc * 2 + (i & 1);
                    const float z = acc[mt * 32 + nt * 4 + i] + bl[n];
                    smH[m * SMH_STRIDE + n] = __uint_as_float(f2tf(__sinf(OMEGA * z)));
                }
        __syncthreads();
    }

    // ================= Head: [128 x 256] @ [256 x 3] + b3 =================
    for (int idx = tid; idx < IMW * OUTC; idx += THREADS) {
        const int p = idx & 127;
        const int o = idx >> 7;
        float sum = b3[o];
#pragma unroll 8
        for (int k = 0; k < HID; ++k)
            sum += smH[p * SMH_STRIDE + k] * W3[k * OUTC + o];
        out[(((size_t)bimg * OUTC + o) * IMH + hrow) * IMW + p] = sum;
    }
}

extern "C" void kernel_launch(void* const* d_in, const int* in_sizes, int n_in,
                              void* d_out, int out_size)
{
    const float* xi = (const float*)d_in[0];
    const float* W0 = (const float*)d_in[1];
    const float* b0 = (const float*)d_in[2];
    const float* W1 = (const float*)d_in[3];
    const float* b1 = (const float*)d_in[4];
    const float* W2 = (const float*)d_in[5];
    const float* b2 = (const float*)d_in[6];
    const float* W3 = (const float*)d_in[7];
    const float* b3 = (const float*)d_in[8];
    float* out = (float*)d_out;

    cudaFuncSetAttribute(nerd_fused_kernel,
                         cudaFuncAttributeMaxDynamicSharedMemorySize, SMEM_BYTES);

    const int n_xi = 2 * FC * XPH * XPW;
    prep_xi_kernel<<<(n_xi + 511) / 512, 512>>>(xi);
    const int n_w = 3200 * HID + 2 * HID * HID;
    prep_w_kernel<<<(n_w + 511) / 512, 512>>>(W0, W1, W2);

    nerd_fused_kernel<<<256, THREADS, SMEM_BYTES>>>(
        W0, b0, b1, b2, W3, b3, out);
}

// round 6
// speedup vs baseline: 1.2871x; 1.2871x over previous
#include <cuda_runtime.h>
#include <cstdint>
#include <cstddef>

// NeRD pixel decoder, fully fused per image row (tf32 mma.sync path — the
// harness compiles PTX at compute_103, so sm_103a-only tcgen05 is unavailable).
//   Layer 0: implicit 5x5 conv as GEMM  [128 x 3200(+2)] @ [.. x 256]
//   Layers 1,2: [128 x 256] @ [256 x 256]
//   Head: [128 x 256] @ [256 x 3]
// One CTA = one (batch, image-row): M=128, N=256. 8 warps, warp tile 64x64.
// Register-prefetch double buffering: LDG next slab -> regs, MMA, STS to the
// other buffer, ONE barrier per iteration.
//
// Bank-conflict rules (derived R2):
//   k-major operand (A/B slabs): frag addr = lc*stride + lr -> stride%32==8
//   m-major operand (smH):       frag addr = lr*stride + lc -> stride%32==4

#define FC   128
#define HID  256
#define OUTC 3
#define IMH  128
#define IMW  128
#define OMEGA 30.0f
#define THREADS 256

#define XPH 132                 // 128 + 2 pad each side (h)
#define XPW 136                 // 128 + 2 pad (w) + 4 -> %32==8

#define SMH_STRIDE 260          // m-major, %32==4
#define SMA_STRIDE 136          // k-major, %32==8
#define SMB_STRIDE 264          // k-major, %32==8

#define SMH_FLOATS (128 * SMH_STRIDE)   // 33280
#define SMA_FLOATS (32  * SMA_STRIDE)   // 4352
#define SMB_FLOATS (32  * SMB_STRIDE)   // 8448
// smA double buffers alias into smH (smH unused during layer 0)
#define SMEM_FLOATS (SMH_FLOATS + 2 * SMB_FLOATS)
#define SMEM_BYTES  (SMEM_FLOATS * 4)   // 200704 B

// ---- persistent scratch (static device arrays; no dynamic alloc) ----
__device__ float g_xi [2 * FC * XPH * XPW];  // [b][c][hp][wp] tf32 bits, padded
__device__ float g_W0t[25 * FC * HID];       // [tap][c][n]    tf32 bits
__device__ float g_W1 [HID * HID];           // [k][n]
__device__ float g_W2 [HID * HID];

__device__ __forceinline__ unsigned f2tf(float f) {
    unsigned u;
    asm("cvt.rna.tf32.f32 %0, %1;" : "=r"(u) : "f"(f));
    return u;
}

// m16n8k8 tf32 mma, fp32 accumulate (fragment layouts per PTX ISA).
__device__ __forceinline__ void mma8(float* c, const unsigned* a, unsigned b0, unsigned b1) {
    asm("mma.sync.aligned.m16n8k8.row.col.f32.tf32.tf32.f32 "
        "{%0,%1,%2,%3}, {%4,%5,%6,%7}, {%8,%9}, {%0,%1,%2,%3};"
        : "+f"(c[0]), "+f"(c[1]), "+f"(c[2]), "+f"(c[3])
        : "r"(a[0]), "r"(a[1]), "r"(a[2]), "r"(a[3]), "r"(b0), "r"(b1));
}

// ================= prep kernels =================
extern "C" __global__ void prep_xi_kernel(const float* __restrict__ xi) {
    int idx = blockIdx.x * blockDim.x + threadIdx.x;
    if (idx >= 2 * FC * XPH * XPW) return;
    const int wp = idx % XPW;
    const int t  = idx / XPW;
    const int hp = t % XPH;
    const int bc = t / XPH;                 // b*FC + c
    const int h = hp - 2, w = wp - 2;
    float v = 0.f;
    if ((unsigned)h < IMH && (unsigned)w < IMW)
        v = xi[((size_t)bc * IMH + h) * IMW + w];
    g_xi[idx] = __uint_as_float(f2tf(v));
}

extern "C" __global__ void prep_w_kernel(const float* __restrict__ W0,
                                         const float* __restrict__ W1,
                                         const float* __restrict__ W2) {
    int idx = blockIdx.x * blockDim.x + threadIdx.x;
    const int NW0 = 25 * FC * HID;          // 819200
    if (idx < NW0) {
        const int n = idx & 255;
        const int t = idx >> 8;             // tap*128 + c
        const int tap = t >> 7, c = t & 127;
        g_W0t[idx] = __uint_as_float(f2tf(W0[(size_t)(c * 25 + tap) * HID + n]));
    } else {
        int j = idx - NW0;
        if (j < HID * HID)          g_W1[j] = __uint_as_float(f2tf(W1[j]));
        else if (j < 2 * HID * HID) g_W2[j - HID * HID] = __uint_as_float(f2tf(W2[j - HID * HID]));
    }
}

// ================= main fused kernel =================
extern "C" __global__ void __launch_bounds__(THREADS, 1)
nerd_fused_kernel(const float* __restrict__ W0f,   // original fp32 W0 (coord rows)
                  const float* __restrict__ b0,
                  const float* __restrict__ b1,
                  const float* __restrict__ b2,
                  const float* __restrict__ W3, const float* __restrict__ b3,
                  float* __restrict__ out)
{
    extern __shared__ float smem[];
    float* smH  = smem;                          // [128][260]
    float* smA0 = smem;                          // alias (layer-0 only)
    float* smA1 = smem + SMA_FLOATS;
    float* smB0 = smem + SMH_FLOATS;
    float* smB1 = smem + SMH_FLOATS + SMB_FLOATS;

    const int tid  = threadIdx.x;
    const int lane = tid & 31;
    const int warp = tid >> 5;                   // 8 warps
    const int wm   = warp >> 2;                  // 0..1 -> m block of 64
    const int wn   = warp & 3;                   // 0..3 -> n block of 64
    const int lr   = lane >> 2;
    const int lc   = lane & 3;

    const int bx   = blockIdx.x;
    const int bimg = bx >> 7;
    const int hrow = bx & 127;

    float acc[128];                              // [mt(4)][nt(8)][4]
#pragma unroll
    for (int i = 0; i < 128; ++i) acc[i] = 0.f;

    // slab address helpers
    // it -> g = it/5 (g = ph*4+cb), pw = it%5; B slab base (contiguous 32KB):
    //   g_W0t + ((ph*5+pw)*128 + cb*32)*256
    // A slab base: g_xi + ((bimg*128 + cb*32)*132 + hrow+ph)*136, row step 132*136

    // ---- prologue: stage B(0) and A(0) directly ----
    {
        const float* bbase = g_W0t;              // ph=0,pw=0,cb=0 -> tap 0, c 0
#pragma unroll
        for (int j = 0; j < 8; ++j) {
            const int idx = tid + j * THREADS;
            const int ci = idx >> 6, f4 = (idx & 63) << 2;
            *reinterpret_cast<float4*>(smB0 + ci * SMB_STRIDE + f4) =
                *reinterpret_cast<const float4*>(bbase + ci * HID + f4);
        }
        const float* abase = g_xi + ((size_t)(bimg * FC) * XPH + hrow) * XPW;
#pragma unroll
        for (int j = 0; j < 5; ++j) {
            const int idx = tid + j * THREADS;
            if (idx < 1088) {
                const int c = idx / 34, f4 = (idx - c * 34) << 2;
                *reinterpret_cast<float4*>(smA0 + c * SMA_STRIDE + f4) =
                    *reinterpret_cast<const float4*>(abase + (size_t)c * (XPH * XPW) + f4);
            }
        }
    }
    __syncthreads();

    // ================= Layer 0: 100 iterations, reg-prefetch pipeline =======
    for (int it = 0; it < 100; ++it) {
        const int g = it / 5, pw = it - g * 5;
        const bool pfB = (it + 1 < 100);
        const bool pfA = (pw == 4) && (g + 1 < 20);

        float4 pb[8];
        if (pfB) {
            const int nit = it + 1;
            const int ng = nit / 5, npw = nit - ng * 5;
            const int nph = ng >> 2, ncb = ng & 3;
            const float* bbase = g_W0t + (size_t)((nph * 5 + npw) * FC + ncb * 32) * HID;
#pragma unroll
            for (int j = 0; j < 8; ++j) {
                const int idx = tid + j * THREADS;
                const int ci = idx >> 6, f4 = (idx & 63) << 2;
                pb[j] = *reinterpret_cast<const float4*>(bbase + ci * HID + f4);
            }
        }
        float4 pa[5];
        if (pfA) {
            const int ng = g + 1;
            const int nph = ng >> 2, ncb = ng & 3;
            const float* abase = g_xi +
                ((size_t)(bimg * FC + ncb * 32) * XPH + hrow + nph) * XPW;
#pragma unroll
            for (int j = 0; j < 5; ++j) {
                const int idx = tid + j * THREADS;
                if (idx < 1088) {
                    const int c = idx / 34, f4 = (idx - c * 34) << 2;
                    pa[j] = *reinterpret_cast<const float4*>(abase + (size_t)c * (XPH * XPW) + f4);
                }
            }
        }

        const float* sA = (g & 1) ? smA1 : smA0;
        const float* sB = (it & 1) ? smB1 : smB0;
#pragma unroll
        for (int kk = 0; kk < 4; ++kk) {
            const int k0 = kk * 8;
            unsigned a[4][4];
#pragma unroll
            for (int mt = 0; mt < 4; ++mt) {
                const int mbase = wm * 64 + mt * 16 + lr + pw;   // halo: wa = m + pw
                a[mt][0] = __float_as_uint(sA[(k0 + lc)     * SMA_STRIDE + mbase]);
                a[mt][1] = __float_as_uint(sA[(k0 + lc)     * SMA_STRIDE + mbase + 8]);
                a[mt][2] = __float_as_uint(sA[(k0 + lc + 4) * SMA_STRIDE + mbase]);
                a[mt][3] = __float_as_uint(sA[(k0 + lc + 4) * SMA_STRIDE + mbase + 8]);
            }
#pragma unroll
            for (int nt = 0; nt < 8; ++nt) {
                const int n0 = wn * 64 + nt * 8 + lr;
                const unsigned bb0 = __float_as_uint(sB[(k0 + lc)     * SMB_STRIDE + n0]);
                const unsigned bb1 = __float_as_uint(sB[(k0 + lc + 4) * SMB_STRIDE + n0]);
#pragma unroll
                for (int mt = 0; mt < 4; ++mt)
                    mma8(&acc[(mt * 8 + nt) * 4], a[mt], bb0, bb1);
            }
        }

        if (pfB) {
            float* dB = ((it + 1) & 1) ? smB1 : smB0;
#pragma unroll
            for (int j = 0; j < 8; ++j) {
                const int idx = tid + j * THREADS;
                const int ci = idx >> 6, f4 = (idx & 63) << 2;
                *reinterpret_cast<float4*>(dB + ci * SMB_STRIDE + f4) = pb[j];
            }
        }
        if (pfA) {
            float* dA = ((g + 1) & 1) ? smA1 : smA0;
#pragma unroll
            for (int j = 0; j < 5; ++j) {
                const int idx = tid + j * THREADS;
                if (idx < 1088) {
                    const int c = idx / 34, f4 = (idx - c * 34) << 2;
                    *reinterpret_cast<float4*>(dA + c * SMA_STRIDE + f4) = pa[j];
                }
            }
        }
        __syncthreads();
    }

    // ---- layer-0 epilogue: + coords*W0[3200:3202] + b0, sin -> smH ----
    {
        const float gy = -1.f + 2.f * (float)hrow * (1.f / 127.f);
#pragma unroll
        for (int mt = 0; mt < 4; ++mt)
#pragma unroll
            for (int nt = 0; nt < 8; ++nt)
#pragma unroll
                for (int i = 0; i < 4; ++i) {
                    const int m = wm * 64 + mt * 16 + lr + ((i >= 2) ? 8 : 0);
                    const int n = wn * 64 + nt * 8 + lc * 2 + (i & 1);
                    const float gx = -1.f + 2.f * (float)m * (1.f / 127.f);
                    float z = acc[(mt * 8 + nt) * 4 + i]
                            + gx * W0f[3200 * HID + n]
                            + gy * W0f[3201 * HID + n]
                            + b0[n];
                    smH[m * SMH_STRIDE + n] = __uint_as_float(f2tf(__sinf(OMEGA * z)));
                }
    }
    __syncthreads();

    // ================= Layers 1 and 2 (reg-prefetch over 8 k-slabs) =========
    for (int L = 0; L < 2; ++L) {
        const float* Wg = L ? g_W2 : g_W1;
        const float* bl = L ? b2 : b1;
#pragma unroll
        for (int i = 0; i < 128; ++i) acc[i] = 0.f;

        // prologue: stage kb=0
#pragma unroll
        for (int j = 0; j < 8; ++j) {
            const int idx = tid + j * THREADS;
            const int ci = idx >> 6, f4 = (idx & 63) << 2;
            *reinterpret_cast<float4*>(smB0 + ci * SMB_STRIDE + f4) =
                *reinterpret_cast<const float4*>(Wg + (size_t)ci * HID + f4);
        }
        __syncthreads();

        for (int kb = 0; kb < 8; ++kb) {
            float4 pb[8];
            if (kb + 1 < 8) {
                const float* wb = Wg + (size_t)(kb + 1) * 32 * HID;
#pragma unroll
                for (int j = 0; j < 8; ++j) {
                    const int idx = tid + j * THREADS;
                    const int ci = idx >> 6, f4 = (idx & 63) << 2;
                    pb[j] = *reinterpret_cast<const float4*>(wb + (size_t)ci * HID + f4);
                }
            }
            const float* sB = (kb & 1) ? smB1 : smB0;
#pragma unroll
            for (int kk = 0; kk < 4; ++kk) {
                const int k0 = kk * 8;
                const int kg = kb * 32 + k0;
                unsigned a[4][4];
#pragma unroll
                for (int mt = 0; mt < 4; ++mt) {
                    const int mbase = wm * 64 + mt * 16 + lr;
                    a[mt][0] = __float_as_uint(smH[(mbase)     * SMH_STRIDE + kg + lc]);
                    a[mt][1] = __float_as_uint(smH[(mbase + 8) * SMH_STRIDE + kg + lc]);
                    a[mt][2] = __float_as_uint(smH[(mbase)     * SMH_STRIDE + kg + lc + 4]);
                    a[mt][3] = __float_as_uint(smH[(mbase + 8) * SMH_STRIDE + kg + lc + 4]);
                }
#pragma unroll
                for (int nt = 0; nt < 8; ++nt) {
                    const int n0 = wn * 64 + nt * 8 + lr;
                    const unsigned bb0 = __float_as_uint(sB[(k0 + lc)     * SMB_STRIDE + n0]);
                    const unsigned bb1 = __float_as_uint(sB[(k0 + lc + 4) * SMB_STRIDE + n0]);
#pragma unroll
                    for (int mt = 0; mt < 4; ++mt)
                        mma8(&acc[(mt * 8 + nt) * 4], a[mt], bb0, bb1);
                }
            }
            if (kb + 1 < 8) {
                float* dB = ((kb + 1) & 1) ? smB1 : smB0;
#pragma unroll
                for (int j = 0; j < 8; ++j) {
                    const int idx = tid + j * THREADS;
                    const int ci = idx >> 6, f4 = (idx & 63) << 2;
                    *reinterpret_cast<float4*>(dB + ci * SMB_STRIDE + f4) = pb[j];
                }
            }
            __syncthreads();
        }

        // epilogue: + bl, sin -> smH (barrier above ensures all reads done)
#pragma unroll
        for (int mt = 0; mt < 4; ++mt)
#pragma unroll
            for (int nt = 0; nt < 8; ++nt)
#pragma unroll
                for (int i = 0; i < 4; ++i) {
                    const int m = wm * 64 + mt * 16 + lr + ((i >= 2) ? 8 : 0);
                    const int n = wn * 64 + nt * 8 + lc * 2 + (i & 1);
                    const float z = acc[(mt * 8 + nt) * 4 + i] + bl[n];
                    smH[m * SMH_STRIDE + n] = __uint_as_float(f2tf(__sinf(OMEGA * z)));
                }
        __syncthreads();
    }

    // ================= Head: [128 x 256] @ [256 x 3] + b3 =================
    for (int idx = tid; idx < IMW * OUTC; idx += THREADS) {
        const int p = idx & 127;
        const int o = idx >> 7;
        float sum = b3[o];
#pragma unroll 8
        for (int k = 0; k < HID; ++k)
            sum += smH[p * SMH_STRIDE + k] * W3[k * OUTC + o];
        out[(((size_t)bimg * OUTC + o) * IMH + hrow) * IMW + p] = sum;
    }
}

extern "C" void kernel_launch(void* const* d_in, const int* in_sizes, int n_in,
                              void* d_out, int out_size)
{
    const float* xi = (const float*)d_in[0];
    const float* W0 = (const float*)d_in[1];
    const float* b0 = (const float*)d_in[2];
    const float* W1 = (const float*)d_in[3];
    const float* b1 = (const float*)d_in[4];
    const float* W2 = (const float*)d_in[5];
    const float* b2 = (const float*)d_in[6];
    const float* W3 = (const float*)d_in[7];
    const float* b3 = (const float*)d_in[8];
    float* out = (float*)d_out;

    cudaFuncSetAttribute(nerd_fused_kernel,
                         cudaFuncAttributeMaxDynamicSharedMemorySize, SMEM_BYTES);

    const int n_xi = 2 * FC * XPH * XPW;
    prep_xi_kernel<<<(n_xi + 511) / 512, 512>>>(xi);
    const int n_w = 25 * FC * HID + 2 * HID * HID;
    prep_w_kernel<<<(n_w + 511) / 512, 512>>>(W0, W1, W2);

    nerd_fused_kernel<<<256, THREADS, SMEM_BYTES>>>(W0, b0, b1, b2, W3, b3, out);
}

// round 8
// speedup vs baseline: 2.3332x; 1.8128x over previous
#include <cuda_runtime.h>
#include <cuda_fp16.h>
#include <cstdint>
#include <cstddef>

// NeRD pixel decoder, fully fused per image row — fp16 mma.sync m16n8k16 path.
// fp16 mantissa == tf32 mantissa (11 bits) but 2x K per mma instruction.
// Weights pre-scaled by 2^8 (exact) so all fp16 weight values are normal
// (kills any FTZ/subnormal hazard); epilogue multiplies acc by 2^-8.
//
//   Layer 0: implicit 5x5 conv GEMM [128 x 3200] @ [3200 x 256], 100 K=32 slabs
//   Layers 1,2: [128 x 256] @ [256 x 256], 8 K=32 slabs each
//   Head: [128 x 256] @ [256 x 3] scalar
// One CTA = one (batch, image-row). 8 warps, warp tile 64x64, acc in fp32.
//
// Fragment bank derivations (fp16, addr32 = addr_half/2):
//   A/smH m-major [m][k]: frag addr32 = (rb+g)*S2 + lc ; S2 % 32 == 4  -> ok
//   A slab stride_half 40 (S2=20): banks (20g+lc) mod 32 all distinct  -> ok
//   B n-major [n][40]:    banks (20g+lc)                               -> ok
//   smH stride_half 264 (S2=132 == 4 mod 32)                           -> ok

#define FC   128
#define HID  256
#define OUTC 3
#define IMH  128
#define IMW  128
#define OMEGA 30.0f
#define THREADS 256
#define WSCALE 256.0f
#define INV_WSCALE 0.00390625f

#define SMH_H 264                   // smH stride (halves)
#define SMA_H 40                    // A slab stride
#define SMB_H 40                    // B slab stride
#define SMH_HALF (128 * SMH_H)      // 33792
#define SMA_HALF (132 * SMA_H)      // 5280
#define SMB_HALF (256 * SMB_H)      // 10240
#define OFF_SMB0 SMH_HALF
#define OFF_SMB1 (SMH_HALF + SMB_HALF)
#define SMEM_BYTES ((SMH_HALF + 2 * SMB_HALF) * 2)   // 108544 B

// ---- persistent scratch: pre-tiled fp16 slabs in exact staging order ----
// g_xiA[(b*4+cb)*132 + hp][(j*132 + wa)*8 + e]   (c = cb*32 + j*8 + e)
__device__ __half g_xiA[2 * 4 * 132 * 4224];     // 8.9 MB
// g_W0s[tap][cb][(j*256 + n)*8 + e]              (c = cb*32 + j*8 + e), *2^8
__device__ __half g_W0s[25 * 4 * 8192];
// g_W1s[kb][(j*256 + n)*8 + e]                   (k = kb*32 + j*8 + e), *2^8
__device__ __half g_W1s[8 * 8192];
__device__ __half g_W2s[8 * 8192];

// m16n8k16 fp16 mma, fp32 accumulate. Fragments (g=lane>>2, t=lane&3):
//   A: a0=(g,2t:2t+1) a1=(g+8,..) a2=(g,2t+8:2t+9) a3=(g+8,..)
//   B: b0=(2t:2t+1, n=g) b1=(2t+8:2t+9, g)
//   C: c0=(g,2t) c1=(g,2t+1) c2=(g+8,2t) c3=(g+8,2t+1)
__device__ __forceinline__ void mma16(float* c, const unsigned* a, unsigned b0, unsigned b1) {
    asm("mma.sync.aligned.m16n8k16.row.col.f32.f16.f16.f32 "
        "{%0,%1,%2,%3}, {%4,%5,%6,%7}, {%8,%9}, {%0,%1,%2,%3};"
        : "+f"(c[0]), "+f"(c[1]), "+f"(c[2]), "+f"(c[3])
        : "r"(a[0]), "r"(a[1]), "r"(a[2]), "r"(a[3]), "r"(b0), "r"(b1));
}

// ================= prep kernels =================
// Transpose xi -> channel-tiled padded fp16, one block per (b, hp).
extern "C" __global__ void prep_xi_kernel(const float* __restrict__ xi) {
    __shared__ __half smT[132 * 137];          // [wa][c], pad 137 (odd stride)
    const int bi = blockIdx.x;
    const int b  = bi / 132, hp = bi - b * 132;
    const int h  = hp - 2;
    const int tid = threadIdx.x;
    const bool hok = (unsigned)h < IMH;
    for (int i = tid; i < 128 * 132; i += THREADS) {
        const int c = i / 132, wi = i - c * 132;
        const int w = wi - 2;
        float v = 0.f;
        if (hok && (unsigned)w < IMW)
            v = xi[(((size_t)b * FC + c) * IMH + h) * IMW + w];
        smT[wi * 137 + c] = __float2half_rn(v);
    }
    __syncthreads();
    for (int i = tid; i < 4 * 4224; i += THREADS) {
        const int cb = i / 4224;               // (R6 bug: was i>>12 with r=i&4095,
        const int r  = i - cb * 4224;          //  but the slab is 4224, not 4096)
        const int e = r & 7, wj = r >> 3;
        const int wa = wj % 132, j = wj / 132;
        const int c = cb * 32 + j * 8 + e;
        g_xiA[(((size_t)b * 4 + cb) * 132 + hp) * 4224 + r] = smT[wa * 137 + c];
    }
}

extern "C" __global__ void prep_w_kernel(const float* __restrict__ W0,
                                         const float* __restrict__ W1,
                                         const float* __restrict__ W2) {
    int idx = blockIdx.x * blockDim.x + threadIdx.x;
    const int NW0 = 25 * 4 * 8192;             // 819200 (slab 8192 = 2^13: shifts ok)
    if (idx < NW0) {
        const int e = idx & 7, n = (idx >> 3) & 255, j = (idx >> 11) & 3;
        const int cb = (idx >> 13) & 3, tap = idx >> 15;
        const int c = cb * 32 + j * 8 + e;
        g_W0s[idx] = __float2half_rn(W0[((size_t)c * 25 + tap) * HID + n] * WSCALE);
    } else {
        int r = idx - NW0;
        if (r >= 2 * 65536) return;
        const int which = r >> 16; r &= 65535;
        const int e = r & 7, n = (r >> 3) & 255, j = (r >> 11) & 3, kb = r >> 13;
        const int k = kb * 32 + j * 8 + e;
        const float v = (which ? W2 : W1)[(size_t)k * HID + n] * WSCALE;
        if (which) g_W2s[r] = __float2half_rn(v);
        else       g_W1s[r] = __float2half_rn(v);
    }
}

// ================= main fused kernel =================
extern "C" __global__ void __launch_bounds__(THREADS, 1)
nerd_fused_kernel(const float* __restrict__ W0f, const float* __restrict__ b0,
                  const float* __restrict__ b1, const float* __restrict__ b2,
                  const float* __restrict__ W3, const float* __restrict__ b3,
                  float* __restrict__ out)
{
    extern __shared__ __half smem[];
    __half* smH  = smem;                       // [128][264]
    __half* smA0 = smem;                       // alias into smH (layer 0 only)
    __half* smA1 = smem + SMA_HALF;
    __half* smB0 = smem + OFF_SMB0;
    __half* smB1 = smem + OFF_SMB1;

    const int tid  = threadIdx.x;
    const int lane = tid & 31, warp = tid >> 5;    // 8 warps
    const int wm = warp >> 2, wn = warp & 3;       // 2 x 4 warp grid, tile 64x64
    const int lr = lane >> 2, lc = lane & 3;
    const int bx = blockIdx.x, bimg = bx >> 7, hrow = bx & 127;

    float acc[128];                                 // [mt4][nt8][4]
#pragma unroll
    for (int i = 0; i < 128; ++i) acc[i] = 0.f;

    // ---- prologue: stage A(0) (ph=0,cb=0) and B(0) (tap=0,cb=0) ----
    {
        const float4* as = (const float4*)(g_xiA + (((size_t)bimg * 4) * 132 + hrow) * 4224);
#pragma unroll
        for (int l = 0; l < 3; ++l) {
            const int idx = tid + l * 256;
            if (idx < 528)
                *(float4*)(smA0 + (idx % 132) * SMA_H + (idx / 132) * 8) = as[idx];
        }
        const float4* bs = (const float4*)(g_W0s);
#pragma unroll
        for (int l = 0; l < 4; ++l)
            *(float4*)(smB0 + tid * SMB_H + l * 8) = bs[tid + l * 256];
    }
    __syncthreads();

    // ================= Layer 0: 100 K=32 slabs (25 taps x 4 cb) =============
    for (int it = 0; it < 100; ++it) {
        const int g = it / 5, pw = it - g * 5;     // g = ph*4 + cb
        const bool pfB = (it + 1 < 100);
        const bool pfA = (pw == 4) && (g + 1 < 20);

        float4 pb[4], pa[3];
        if (pfB) {
            const int nit = it + 1, ng = nit / 5, npw = nit - ng * 5;
            const int nph = ng >> 2, ncb = ng & 3;
            const float4* src = (const float4*)(g_W0s + ((size_t)(nph * 5 + npw) * 4 + ncb) * 8192);
#pragma unroll
            for (int l = 0; l < 4; ++l) pb[l] = src[tid + l * 256];
        }
        if (pfA) {
            const int ng = g + 1, nph = ng >> 2, ncb = ng & 3;
            const float4* src = (const float4*)(g_xiA + (((size_t)bimg * 4 + ncb) * 132 + hrow + nph) * 4224);
#pragma unroll
            for (int l = 0; l < 3; ++l) {
                const int idx = tid + l * 256;
                if (idx < 528) pa[l] = src[idx];
            }
        }

        const __half* sA = (g & 1) ? smA1 : smA0;
        const __half* sB = (it & 1) ? smB1 : smB0;
#pragma unroll
        for (int kk = 0; kk < 2; ++kk) {
            const int kh = kk * 16 + 2 * lc;
            unsigned a[4][4];
#pragma unroll
            for (int mt = 0; mt < 4; ++mt) {
                const int rb = wm * 64 + mt * 16 + lr + pw;    // wa = m + pw
                a[mt][0] = *(const unsigned*)(sA + rb * SMA_H + kh);
                a[mt][1] = *(const unsigned*)(sA + (rb + 8) * SMA_H + kh);
                a[mt][2] = *(const unsigned*)(sA + rb * SMA_H + kh + 8);
                a[mt][3] = *(const unsigned*)(sA + (rb + 8) * SMA_H + kh + 8);
            }
#pragma unroll
            for (int nt = 0; nt < 8; ++nt) {
                const int n0 = wn * 64 + nt * 8 + lr;
                const unsigned bb0 = *(const unsigned*)(sB + n0 * SMB_H + kh);
                const unsigned bb1 = *(const unsigned*)(sB + n0 * SMB_H + kh + 8);
#pragma unroll
                for (int mt = 0; mt < 4; ++mt)
                    mma16(&acc[(mt * 8 + nt) * 4], a[mt], bb0, bb1);
            }
        }

        if (pfB) {
            __half* dB = ((it + 1) & 1) ? smB1 : smB0;
#pragma unroll
            for (int l = 0; l < 4; ++l)
                *(float4*)(dB + tid * SMB_H + l * 8) = pb[l];
        }
        if (pfA) {
            __half* dA = ((g + 1) & 1) ? smA1 : smA0;
#pragma unroll
            for (int l = 0; l < 3; ++l) {
                const int idx = tid + l * 256;
                if (idx < 528)
                    *(float4*)(dA + (idx % 132) * SMA_H + (idx / 132) * 8) = pa[l];
            }
        }
        __syncthreads();
    }

    // ---- layer-0 epilogue: acc/256 + coords + b0, sin -> smH (fp16) ----
    {
        const float gy = -1.f + 2.f * (float)hrow * (1.f / 127.f);
#pragma unroll
        for (int mt = 0; mt < 4; ++mt)
#pragma unroll
            for (int nt = 0; nt < 8; ++nt)
#pragma unroll
                for (int hf = 0; hf < 2; ++hf) {
                    const int m = wm * 64 + mt * 16 + lr + hf * 8;
                    const int n0 = wn * 64 + nt * 8 + lc * 2;
                    const float gx = -1.f + 2.f * (float)m * (1.f / 127.f);
                    const float z0 = acc[(mt * 8 + nt) * 4 + hf * 2 + 0] * INV_WSCALE
                                   + gx * W0f[3200 * HID + n0] + gy * W0f[3201 * HID + n0] + b0[n0];
                    const float z1 = acc[(mt * 8 + nt) * 4 + hf * 2 + 1] * INV_WSCALE
                                   + gx * W0f[3200 * HID + n0 + 1] + gy * W0f[3201 * HID + n0 + 1] + b0[n0 + 1];
                    *(__half2*)(smH + m * SMH_H + n0) =
                        __floats2half2_rn(__sinf(OMEGA * z0), __sinf(OMEGA * z1));
                }
    }
    __syncthreads();

    // ================= Layers 1 and 2 =================
    for (int L = 0; L < 2; ++L) {
        const __half* Ws = L ? g_W2s : g_W1s;
        const float* bl = L ? b2 : b1;
#pragma unroll
        for (int i = 0; i < 128; ++i) acc[i] = 0.f;

        {
            const float4* src = (const float4*)Ws;
#pragma unroll
            for (int l = 0; l < 4; ++l)
                *(float4*)(smB0 + tid * SMB_H + l * 8) = src[tid + l * 256];
        }
        __syncthreads();

        for (int kb = 0; kb < 8; ++kb) {
            float4 pb[4];
            if (kb + 1 < 8) {
                const float4* src = (const float4*)(Ws + (size_t)(kb + 1) * 8192);
#pragma unroll
                for (int l = 0; l < 4; ++l) pb[l] = src[tid + l * 256];
            }
            const __half* sB = (kb & 1) ? smB1 : smB0;
#pragma unroll
            for (int kk = 0; kk < 2; ++kk) {
                const int khg = kb * 32 + kk * 16 + 2 * lc;   // global k in smH
                const int khb = kk * 16 + 2 * lc;             // k within B slab
                unsigned a[4][4];
#pragma unroll
                for (int mt = 0; mt < 4; ++mt) {
                    const int rb = wm * 64 + mt * 16 + lr;
                    a[mt][0] = *(const unsigned*)(smH + rb * SMH_H + khg);
                    a[mt][1] = *(const unsigned*)(smH + (rb + 8) * SMH_H + khg);
                    a[mt][2] = *(const unsigned*)(smH + rb * SMH_H + khg + 8);
                    a[mt][3] = *(const unsigned*)(smH + (rb + 8) * SMH_H + khg + 8);
                }
#pragma unroll
                for (int nt = 0; nt < 8; ++nt) {
                    const int n0 = wn * 64 + nt * 8 + lr;
                    const unsigned bb0 = *(const unsigned*)(sB + n0 * SMB_H + khb);
                    const unsigned bb1 = *(const unsigned*)(sB + n0 * SMB_H + khb + 8);
#pragma unroll
                    for (int mt = 0; mt < 4; ++mt)
                        mma16(&acc[(mt * 8 + nt) * 4], a[mt], bb0, bb1);
                }
            }
            if (kb + 1 < 8) {
                __half* dB = ((kb + 1) & 1) ? smB1 : smB0;
#pragma unroll
                for (int l = 0; l < 4; ++l)
                    *(float4*)(dB + tid * SMB_H + l * 8) = pb[l];
            }
            __syncthreads();
        }

        // epilogue: acc/256 + bl, sin -> smH
#pragma unroll
        for (int mt = 0; mt < 4; ++mt)
#pragma unroll
            for (int nt = 0; nt < 8; ++nt)
#pragma unroll
                for (int hf = 0; hf < 2; ++hf) {
                    const int m = wm * 64 + mt * 16 + lr + hf * 8;
                    const int n0 = wn * 64 + nt * 8 + lc * 2;
                    const float z0 = acc[(mt * 8 + nt) * 4 + hf * 2 + 0] * INV_WSCALE + bl[n0];
                    const float z1 = acc[(mt * 8 + nt) * 4 + hf * 2 + 1] * INV_WSCALE + bl[n0 + 1];
                    *(__half2*)(smH + m * SMH_H + n0) =
                        __floats2half2_rn(__sinf(OMEGA * z0), __sinf(OMEGA * z1));
                }
        __syncthreads();
    }

    // ================= Head: [128 x 256] @ [256 x 3] + b3 =================
    for (int idx = tid; idx < IMW * OUTC; idx += THREADS) {
        const int p = idx & 127, o = idx >> 7;
        float sum = b3[o];
#pragma unroll 4
        for (int k = 0; k < HID; k += 2) {
            const float2 f = __half22float2(*(const __half2*)(smH + p * SMH_H + k));
            sum += f.x * W3[k * OUTC + o] + f.y * W3[(k + 1) * OUTC + o];
        }
        out[(((size_t)bimg * OUTC + o) * IMH + hrow) * IMW + p] = sum;
    }
}

extern "C" void kernel_launch(void* const* d_in, const int* in_sizes, int n_in,
                              void* d_out, int out_size)
{
    const float* xi = (const float*)d_in[0];
    const float* W0 = (const float*)d_in[1];
    const float* b0 = (const float*)d_in[2];
    const float* W1 = (const float*)d_in[3];
    const float* b1 = (const float*)d_in[4];
    const float* W2 = (const float*)d_in[5];
    const float* b2 = (const float*)d_in[6];
    const float* W3 = (const float*)d_in[7];
    const float* b3 = (const float*)d_in[8];
    float* out = (float*)d_out;

    cudaFuncSetAttribute(nerd_fused_kernel,
                         cudaFuncAttributeMaxDynamicSharedMemorySize, SMEM_BYTES);

    prep_xi_kernel<<<2 * 132, THREADS>>>(xi);
    const int n_w = 25 * 4 * 8192 + 2 * 65536;
    prep_w_kernel<<<(n_w + THREADS - 1) / THREADS, THREADS>>>(W0, W1, W2);

    nerd_fused_kernel<<<256, THREADS, SMEM_BYTES>>>(W0, b0, b1, b2, W3, b3, out);
}

// round 9
// speedup vs baseline: 2.4053x; 1.0309x over previous
#include <cuda_runtime.h>
#include <cuda_fp16.h>
#include <cstdint>
#include <cstddef>

// NeRD pixel decoder, fully fused per image row — fp16 mma.sync m16n8k16,
// ldmatrix.x4 fragment loads, 3-stage cp.async staging pipeline.
// Weights pre-scaled by 2^8 (exact); epilogue multiplies acc by 2^-8.
//
//   Layer 0: implicit 5x5 conv GEMM [128 x 3200] @ [3200 x 256], 100 K=32 slabs
//   Layers 1,2: [128 x 256] @ [256 x 256], 8 K=32 slabs each
//   Head: [128 x 256] @ [256 x 3] scalar
// One CTA = one (batch, image-row). 8 warps, warp tile 64x64, acc fp32.
//
// ldmatrix bank checks (8-row wavefronts, 16B/row):
//   A/B slabs stride 40 halves = 20 words: banks {20r..20r+3 mod 32} distinct
//   smH stride 264 halves = 132 words (≡4 mod 32): banks {4r..4r+3} distinct

#define FC   128
#define HID  256
#define OUTC 3
#define IMH  128
#define IMW  128
#define OMEGA 30.0f
#define THREADS 256
#define WSCALE 256.0f
#define INV_WSCALE 0.00390625f

#define SMH_H 264                   // smH stride (halves)
#define SMA_H 40                    // A slab stride
#define SMB_H 40                    // B slab stride
#define SMH_HALF (128 * SMH_H)      // 33792
#define SMA_HALF (132 * SMA_H)      // 5280
#define SMB_HALF (256 * SMB_H)      // 10240
#define OFF_B(st) (SMH_HALF + (st) * SMB_HALF)
#define SMEM_BYTES ((SMH_HALF + 3 * SMB_HALF) * 2)   // 129024 B

// ---- persistent scratch: pre-tiled fp16 slabs in exact staging order ----
__device__ __half g_xiA[2 * 4 * 132 * 4224];     // [(b*4+cb)*132+hp][(j*132+wa)*8+e]
__device__ __half g_W0s[25 * 4 * 8192];          // [tap][cb][(j*256+n)*8+e] *2^8
__device__ __half g_W1s[8 * 8192];               // [kb][(j*256+n)*8+e]      *2^8
__device__ __half g_W2s[8 * 8192];

__device__ __forceinline__ void mma16(float* c, const unsigned* a, unsigned b0, unsigned b1) {
    asm("mma.sync.aligned.m16n8k16.row.col.f32.f16.f16.f32 "
        "{%0,%1,%2,%3}, {%4,%5,%6,%7}, {%8,%9}, {%0,%1,%2,%3};"
        : "+f"(c[0]), "+f"(c[1]), "+f"(c[2]), "+f"(c[3])
        : "r"(a[0]), "r"(a[1]), "r"(a[2]), "r"(a[3]), "r"(b0), "r"(b1));
}

__device__ __forceinline__ void ldsm4(unsigned& r0, unsigned& r1, unsigned& r2,
                                      unsigned& r3, unsigned addr) {
    asm volatile("ldmatrix.sync.aligned.m8n8.x4.shared.b16 {%0,%1,%2,%3}, [%4];"
                 : "=r"(r0), "=r"(r1), "=r"(r2), "=r"(r3) : "r"(addr));
}

__device__ __forceinline__ void cpa16(unsigned dst, const void* src) {
    asm volatile("cp.async.ca.shared.global [%0], [%1], 16;" :: "r"(dst), "l"(src));
}
#define CP_COMMIT asm volatile("cp.async.commit_group;" ::: "memory")
#define CP_WAIT(n) asm volatile("cp.async.wait_group %0;" :: "n"(n) : "memory")

// ================= prep kernels =================
// Direct scatter, one block per (b, cb, hp): grid 1056 (fixes grid-bound occ).
extern "C" __global__ void prep_xi_kernel(const float* __restrict__ xi) {
    const int bi = blockIdx.x;
    const int hp = bi % 132;
    const int t  = bi / 132;
    const int cb = t & 3, b = t >> 2;
    const int h  = hp - 2;
    const bool hok = (unsigned)h < IMH;
    __half* dst = g_xiA + (((size_t)(b * 4 + cb)) * 132 + hp) * 4224;
    for (int r = threadIdx.x; r < 4224; r += blockDim.x) {
        const int e = r & 7, wj = r >> 3;
        const int wa = wj % 132, j = wj / 132;
        const int c = cb * 32 + j * 8 + e;
        const int w = wa - 2;
        float v = 0.f;
        if (hok && (unsigned)w < IMW)
            v = xi[(((size_t)b * FC + c) * IMH + h) * IMW + w];
        dst[r] = __float2half_rn(v);
    }
}

extern "C" __global__ void prep_w_kernel(const float* __restrict__ W0,
                                         const float* __restrict__ W1,
                                         const float* __restrict__ W2) {
    int idx = blockIdx.x * blockDim.x + threadIdx.x;
    const int NW0 = 25 * 4 * 8192;             // slab 8192 = 2^13: shifts valid
    if (idx < NW0) {
        const int e = idx & 7, n = (idx >> 3) & 255, j = (idx >> 11) & 3;
        const int cb = (idx >> 13) & 3, tap = idx >> 15;
        const int c = cb * 32 + j * 8 + e;
        g_W0s[idx] = __float2half_rn(W0[((size_t)c * 25 + tap) * HID + n] * WSCALE);
    } else {
        int r = idx - NW0;
        if (r >= 2 * 65536) return;
        const int which = r >> 16; r &= 65535;
        const int e = r & 7, n = (r >> 3) & 255, j = (r >> 11) & 3, kb = r >> 13;
        const int k = kb * 32 + j * 8 + e;
        const float v = (which ? W2 : W1)[(size_t)k * HID + n] * WSCALE;
        if (which) g_W2s[r] = __float2half_rn(v);
        else       g_W1s[r] = __float2half_rn(v);
    }
}

// ================= main fused kernel =================
extern "C" __global__ void __launch_bounds__(THREADS, 1)
nerd_fused_kernel(const float* __restrict__ W0f, const float* __restrict__ b0,
                  const float* __restrict__ b1, const float* __restrict__ b2,
                  const float* __restrict__ W3, const float* __restrict__ b3,
                  float* __restrict__ out)
{
    extern __shared__ __half smem[];
    __half* smH = smem;                              // [128][264]
    const unsigned sbase = (unsigned)__cvta_generic_to_shared(smem);

    const int tid  = threadIdx.x;
    const int lane = tid & 31, warp = tid >> 5;      // 8 warps
    const int wm = warp >> 2, wn = warp & 3;         // 2 x 4 grid, warp tile 64x64
    const int lr = lane >> 2, lc = lane & 3;
    const int l15 = lane & 15, lhi = lane >> 4;      // ldmatrix lane split
    const int bx = blockIdx.x, bimg = bx >> 7, hrow = bx & 127;

    float acc[128];                                  // [mt4][nt8][4]
#pragma unroll
    for (int i = 0; i < 128; ++i) acc[i] = 0.f;

    // ---- staging helpers (cp.async) ----
    auto stage_B0 = [&](int s) {                     // layer-0 B slab for iter s
        const int g = s / 5, pw = s - g * 5;
        const int ph = g >> 2, cb = g & 3;
        const __half* src = g_W0s + ((size_t)(ph * 5 + pw) * 4 + cb) * 8192;
        const unsigned dst = sbase + OFF_B(s % 3) * 2;
#pragma unroll
        for (int l = 0; l < 4; ++l)
            cpa16(dst + (tid * SMB_H + l * 8) * 2, src + ((size_t)l * 256 + tid) * 8);
    };
    auto stage_BL = [&](const __half* Ws, int kb) {  // layers 1/2
        const __half* src = Ws + (size_t)kb * 8192;
        const unsigned dst = sbase + OFF_B(kb % 3) * 2;
#pragma unroll
        for (int l = 0; l < 4; ++l)
            cpa16(dst + (tid * SMB_H + l * 8) * 2, src + ((size_t)l * 256 + tid) * 8);
    };
    auto stage_A = [&](int g) {                      // xi slab for group g = ph*4+cb
        const int ph = g >> 2, cb = g & 3;
        const __half* src = g_xiA + (((size_t)(bimg * 4 + cb)) * 132 + hrow + ph) * 4224;
        const unsigned dst = sbase + ((g & 1) * SMA_HALF) * 2;
#pragma unroll
        for (int l = 0; l < 3; ++l) {
            const int idx = tid + l * 256;
            if (idx < 528)
                cpa16(dst + ((idx % 132) * SMA_H + (idx / 132) * 8) * 2, src + (size_t)idx * 8);
        }
    };

    // ---- prologue: groups 0 (A0+B0) and 1 (B1) ----
    stage_A(0); stage_B0(0); CP_COMMIT;
    stage_B0(1); CP_COMMIT;

    // ================= Layer 0: 100 K=32 slabs, 3-stage pipeline =============
    for (int s = 0; s < 100; ++s) {
        const int g = s / 5, pw = s - g * 5;
        CP_WAIT(1);                                  // group s complete
        __syncthreads();                             // all warps done with iter s-1
        if (s + 2 < 100) stage_B0(s + 2);
        if (pw == 3 && g + 1 < 20) stage_A(g + 1);
        CP_COMMIT;

        const unsigned aB = sbase + ((g & 1) * SMA_HALF) * 2;
        const unsigned bB = sbase + OFF_B(s % 3) * 2;
#pragma unroll
        for (int kk = 0; kk < 2; ++kk) {
            const int col = kk * 16 + lhi * 8;
            unsigned a[4][4];
#pragma unroll
            for (int mt = 0; mt < 4; ++mt) {
                const int row = wm * 64 + mt * 16 + l15 + pw;   // halo shift
                ldsm4(a[mt][0], a[mt][1], a[mt][2], a[mt][3],
                      aB + (row * SMA_H + col) * 2);
            }
#pragma unroll
            for (int np = 0; np < 4; ++np) {                    // nt pairs
                unsigned b0a, b0b, b1a, b1b;
                const int nrow = wn * 64 + np * 16 + l15;
                ldsm4(b0a, b0b, b1a, b1b, bB + (nrow * SMB_H + col) * 2);
#pragma unroll
                for (int mt = 0; mt < 4; ++mt) {
                    mma16(&acc[(mt * 8 + 2 * np) * 4],     a[mt], b0a, b1a);
                    mma16(&acc[(mt * 8 + 2 * np + 1) * 4], a[mt], b0b, b1b);
                }
            }
        }
    }
    CP_WAIT(0);
    __syncthreads();

    // ---- layer-0 epilogue: acc/256 + coords + b0, sin -> smH (fp16) ----
    {
        const float gy = -1.f + 2.f * (float)hrow * (1.f / 127.f);
#pragma unroll
        for (int mt = 0; mt < 4; ++mt)
#pragma unroll
            for (int nt = 0; nt < 8; ++nt)
#pragma unroll
                for (int hf = 0; hf < 2; ++hf) {
                    const int m = wm * 64 + mt * 16 + lr + hf * 8;
                    const int n0 = wn * 64 + nt * 8 + lc * 2;
                    const float gx = -1.f + 2.f * (float)m * (1.f / 127.f);
                    const float z0 = acc[(mt * 8 + nt) * 4 + hf * 2 + 0] * INV_WSCALE
                                   + gx * W0f[3200 * HID + n0] + gy * W0f[3201 * HID + n0] + b0[n0];
                    const float z1 = acc[(mt * 8 + nt) * 4 + hf * 2 + 1] * INV_WSCALE
                                   + gx * W0f[3200 * HID + n0 + 1] + gy * W0f[3201 * HID + n0 + 1] + b0[n0 + 1];
                    *(__half2*)(smH + m * SMH_H + n0) =
                        __floats2half2_rn(__sinf(OMEGA * z0), __sinf(OMEGA * z1));
                }
    }
    __syncthreads();

    // ================= Layers 1 and 2 (3-stage pipeline over 8 k-slabs) ======
    for (int L = 0; L < 2; ++L) {
        const __half* Ws = L ? g_W2s : g_W1s;
        const float* bl = L ? b2 : b1;
#pragma unroll
        for (int i = 0; i < 128; ++i) acc[i] = 0.f;

        stage_BL(Ws, 0); CP_COMMIT;
        stage_BL(Ws, 1); CP_COMMIT;

        for (int kb = 0; kb < 8; ++kb) {
            CP_WAIT(1);
            __syncthreads();
            if (kb + 2 < 8) stage_BL(Ws, kb + 2);
            CP_COMMIT;

            const unsigned bB = sbase + OFF_B(kb % 3) * 2;
#pragma unroll
            for (int kk = 0; kk < 2; ++kk) {
                const int colH = kb * 32 + kk * 16 + lhi * 8;   // k in smH
                const int colB = kk * 16 + lhi * 8;             // k in B slab
                unsigned a[4][4];
#pragma unroll
                for (int mt = 0; mt < 4; ++mt) {
                    const int row = wm * 64 + mt * 16 + l15;
                    ldsm4(a[mt][0], a[mt][1], a[mt][2], a[mt][3],
                          sbase + (row * SMH_H + colH) * 2);
                }
#pragma unroll
                for (int np = 0; np < 4; ++np) {
                    unsigned b0a, b0b, b1a, b1b;
                    const int nrow = wn * 64 + np * 16 + l15;
                    ldsm4(b0a, b0b, b1a, b1b, bB + (nrow * SMB_H + colB) * 2);
#pragma unroll
                    for (int mt = 0; mt < 4; ++mt) {
                        mma16(&acc[(mt * 8 + 2 * np) * 4],     a[mt], b0a, b1a);
                        mma16(&acc[(mt * 8 + 2 * np + 1) * 4], a[mt], b0b, b1b);
                    }
                }
            }
        }
        CP_WAIT(0);
        __syncthreads();

        // epilogue: acc/256 + bl, sin -> smH
#pragma unroll
        for (int mt = 0; mt < 4; ++mt)
#pragma unroll
            for (int nt = 0; nt < 8; ++nt)
#pragma unroll
                for (int hf = 0; hf < 2; ++hf) {
                    const int m = wm * 64 + mt * 16 + lr + hf * 8;
                    const int n0 = wn * 64 + nt * 8 + lc * 2;
                    const float z0 = acc[(mt * 8 + nt) * 4 + hf * 2 + 0] * INV_WSCALE + bl[n0];
                    const float z1 = acc[(mt * 8 + nt) * 4 + hf * 2 + 1] * INV_WSCALE + bl[n0 + 1];
                    *(__half2*)(smH + m * SMH_H + n0) =
                        __floats2half2_rn(__sinf(OMEGA * z0), __sinf(OMEGA * z1));
                }
        __syncthreads();
    }

    // ================= Head: [128 x 256] @ [256 x 3] + b3 =================
    for (int idx = tid; idx < IMW * OUTC; idx += THREADS) {
        const int p = idx & 127, o = idx >> 7;
        float sum = b3[o];
#pragma unroll 4
        for (int k = 0; k < HID; k += 2) {
            const float2 f = __half22float2(*(const __half2*)(smH + p * SMH_H + k));
            sum += f.x * W3[k * OUTC + o] + f.y * W3[(k + 1) * OUTC + o];
        }
        out[(((size_t)bimg * OUTC + o) * IMH + hrow) * IMW + p] = sum;
    }
}

extern "C" void kernel_launch(void* const* d_in, const int* in_sizes, int n_in,
                              void* d_out, int out_size)
{
    const float* xi = (const float*)d_in[0];
    const float* W0 = (const float*)d_in[1];
    const float* b0 = (const float*)d_in[2];
    const float* W1 = (const float*)d_in[3];
    const float* b1 = (const float*)d_in[4];
    const float* W2 = (const float*)d_in[5];
    const float* b2 = (const float*)d_in[6];
    const float* W3 = (const float*)d_in[7];
    const float* b3 = (const float*)d_in[8];
    float* out = (float*)d_out;

    cudaFuncSetAttribute(nerd_fused_kernel,
                         cudaFuncAttributeMaxDynamicSharedMemorySize, SMEM_BYTES);

    prep_xi_kernel<<<2 * 4 * 132, 128>>>(xi);
    const int n_w = 25 * 4 * 8192 + 2 * 65536;
    prep_w_kernel<<<(n_w + 255) / 256, 256>>>(W0, W1, W2);

    nerd_fused_kernel<<<256, THREADS, SMEM_BYTES>>>(W0, b0, b1, b2, W3, b3, out);
}